// round 4
// baseline (speedup 1.0000x reference)
#include <cuda_runtime.h>

// Trilinear resample (B=4, D=64, H=64, W=64, C=32) fp32, identity theta.
// f = 62*i/63 => i0 = max(i-1,0), frac t = 1 - i/63 (t=0 at i=0).
//
// Warp-shuffle column scheme:
//   lane = c4 (0..7) + 8*j (j=0..3);  column x = 3*seg + j  (seg = 0..20)
//   Each lane loads the 4 (y,z)-corner float4s of its column, computes the
//   bilinear g(x). g(x-1) comes from shfl_up(8). Lanes j>=1 emit
//   out(x) = (1-t)*g(x-1) + t*g(x), t = 1 - x/63. Segment 0, j==0 lanes
//   emit out(0) = g(0). Per warp: 16 load-wavefronts -> 24(+) outputs.

#define B_ 4
#define D_ 64
#define H_ 64
#define W_ 64
#define C4_ 8
#define SEGS_ 21   // columns 3*seg + j cover x = 0..63

__global__ __launch_bounds__(256) void trilerp_shfl_kernel(
    const float4* __restrict__ in, float4* __restrict__ out)
{
    const int tid  = blockIdx.x * blockDim.x + threadIdx.x;
    const int lane = tid & 31;
    const int gw   = tid >> 5;          // global warp id

    const int c4  = lane & (C4_ - 1);
    const int j   = lane >> 3;          // 0..3
    const int seg = gw % SEGS_;
    const int rem = gw / SEGS_;
    const int h   = rem & (H_ - 1);
    const int d   = (rem >> 6) & (D_ - 1);
    const int b   = rem >> 12;

    const int x = 3 * seg + j;          // 0..63

    // (y,z) bilinear weights (identical math to the passing R1 kernel)
    const float fy = (float)h * (62.0f / 63.0f);
    const float fz = (float)d * (62.0f / 63.0f);
    const int y0 = max(h - 1, 0);
    const int z0 = max(d - 1, 0);
    const float ty = fy - (float)y0;
    const float tz = fz - (float)z0;
    const float sy = 1.0f - ty;
    const float sz = 1.0f - tz;
    const float q00 = sy * sz;
    const float q10 = ty * sz;
    const float q01 = sy * tz;
    const float q11 = ty * tz;

    const long rowY = (long)W_ * C4_;
    const long rowZ = (long)H_ * W_ * C4_;
    const float4* p = in + ((((long)b * D_ + z0) * H_ + y0) * W_ + x) * C4_ + c4;

    // 4 independent corner loads for this lane's column
    const float4 v00 = __ldg(p);
    const float4 v10 = __ldg(p + rowY);
    const float4 v01 = __ldg(p + rowZ);
    const float4 v11 = __ldg(p + rowZ + rowY);

    float4 g;
    g.x = fmaf(q11, v11.x, fmaf(q01, v01.x, fmaf(q10, v10.x, q00 * v00.x)));
    g.y = fmaf(q11, v11.y, fmaf(q01, v01.y, fmaf(q10, v10.y, q00 * v00.y)));
    g.z = fmaf(q11, v11.z, fmaf(q01, v01.z, fmaf(q10, v10.z, q00 * v00.z)));
    g.w = fmaf(q11, v11.w, fmaf(q01, v01.w, fmaf(q10, v10.w, q00 * v00.w)));

    // g(x-1) from the lane 8 positions down (same c4, previous column)
    float4 gp;
    gp.x = __shfl_up_sync(0xFFFFFFFFu, g.x, 8);
    gp.y = __shfl_up_sync(0xFFFFFFFFu, g.y, 8);
    gp.z = __shfl_up_sync(0xFFFFFFFFu, g.z, 8);
    gp.w = __shfl_up_sync(0xFFFFFFFFu, g.w, 8);

    const long vox = (((long)b * D_ + d) * H_ + h) * W_;

    if (j > 0) {
        // out(x) = (1-t)*g(x-1) + t*g(x), t = 1 - x/63 (x >= 1 here)
        const float t = 1.0f - (float)x * (1.0f / 63.0f);
        const float s = 1.0f - t;
        float4 r;
        r.x = fmaf(t, g.x, s * gp.x);
        r.y = fmaf(t, g.y, s * gp.y);
        r.z = fmaf(t, g.z, s * gp.z);
        r.w = fmaf(t, g.w, s * gp.w);
        out[(vox + x) * C4_ + c4] = r;
    } else if (seg == 0) {
        // w = 0: t = 0, x0 = 0 => out(0) = g(0) (this lane's column is x=0)
        out[vox * C4_ + c4] = g;
    }
}

extern "C" void kernel_launch(void* const* d_in, const int* in_sizes, int n_in,
                              void* d_out, int out_size)
{
    const float4* in = (const float4*)d_in[0];
    float4* out = (float4*)d_out;
    const long total_warps = (long)B_ * D_ * H_ * SEGS_;   // 344064
    const int threads = 256;                               // 8 warps/block
    const int blocks = (int)(total_warps / 8);             // 43008
    trilerp_shfl_kernel<<<blocks, threads>>>(in, out);
}

// round 5
// speedup vs baseline: 1.1400x; 1.1400x over previous
#include <cuda_runtime.h>

// Trilinear resample (B=4, D=64, H=64, W=64, C=32) fp32, identity theta.
// f = 62*i/63 => i0 = max(i-1,0), t(i) = 1 - i/63 (t=0 at i=0).
//
// Warp layout: lane = c4(0..7) + 8*j (j=0..3); column x = 3*seg + j.
// Each lane serves TWO output rows h0=2p, h1=2p+1 (they share the middle
// y-row): loads 3 y-rows x 2 z-planes (6 float4), computes bilinears
// g_h0(x), g_h1(x); g(x-1) via shfl_up(8); lanes j>=1 emit
// out(h,x) = (x/63)*g(x-1) + (1-x/63)*g(x). seg0/j0 lanes emit x=0 (= g(0)).
// Per warp: 24 load wavefronts -> 48 outputs (0.5 lines/output).

#define B_ 4
#define D_ 64
#define H_ 64
#define W_ 64
#define C4_ 8
#define SEGS_ 21

__global__ __launch_bounds__(256) void trilerp_hp_kernel(
    const float4* __restrict__ in, float4* __restrict__ out)
{
    const int lane = threadIdx.x & 31;
    const int wid  = threadIdx.x >> 5;       // 0..7
    const int c4 = lane & (C4_ - 1);
    const int j  = lane >> 3;                // 0..3

    const int seg = blockIdx.x;              // 0..20  (no mod!)
    const int by  = blockIdx.y;              // 0..1023
    const int pg  = by & 3;
    const int d   = (by >> 2) & (D_ - 1);
    const int b   = by >> 8;
    const int p   = pg * 8 + wid;            // 0..31  (h-pair)
    const int h0  = 2 * p;
    const int x   = 3 * seg + j;             // 0..63

    // z weights
    const float fz = (float)d * (62.0f / 63.0f);
    const int z0 = max(d - 1, 0);
    const float tz = fz - (float)z0;
    const float sz = 1.0f - tz;

    const long rowY = (long)W_ * C4_;
    const long rowZ = (long)H_ * W_ * C4_;
    // base at (b, z0, y=0, x, c4)
    const float4* pb = in + (((long)b * D_ + z0) * (long)H_ * W_ + x) * C4_ + c4;

    float4 g0, g1;   // bilinear (y,z) blends for rows h0, h1 at column x

    if (p == 0) {
        // h0=0 (ty0=0), h1=1 (ty1=62/63); both use y-rows {0,1}: 4 loads
        const float4 r0z0 = __ldg(pb);
        const float4 r1z0 = __ldg(pb + rowY);
        const float4 r0z1 = __ldg(pb + rowZ);
        const float4 r1z1 = __ldg(pb + rowZ + rowY);
        // g0: ty=0 -> pure z-lerp of row0
        g0.x = fmaf(tz, r0z1.x, sz * r0z0.x);
        g0.y = fmaf(tz, r0z1.y, sz * r0z0.y);
        g0.z = fmaf(tz, r0z1.z, sz * r0z0.z);
        g0.w = fmaf(tz, r0z1.w, sz * r0z0.w);
        const float ty1 = 62.0f / 63.0f;
        const float sy1 = 1.0f - ty1;
        const float a = sy1 * sz, bw = ty1 * sz, c = sy1 * tz, e = ty1 * tz;
        g1.x = fmaf(e, r1z1.x, fmaf(c, r0z1.x, fmaf(bw, r1z0.x, a * r0z0.x)));
        g1.y = fmaf(e, r1z1.y, fmaf(c, r0z1.y, fmaf(bw, r1z0.y, a * r0z0.y)));
        g1.z = fmaf(e, r1z1.z, fmaf(c, r0z1.z, fmaf(bw, r1z0.z, a * r0z0.z)));
        g1.w = fmaf(e, r1z1.w, fmaf(c, r0z1.w, fmaf(bw, r1z0.w, a * r0z0.w)));
    } else {
        // rows 2p-1, 2p, 2p+1; g0 uses (2p-1,2p), g1 uses (2p,2p+1)
        const float4* pr = pb + (long)(h0 - 1) * rowY;
        const float4 L0z0 = __ldg(pr);
        const float4 L1z0 = __ldg(pr + rowY);
        const float4 L2z0 = __ldg(pr + 2 * rowY);
        const float4 L0z1 = __ldg(pr + rowZ);
        const float4 L1z1 = __ldg(pr + rowZ + rowY);
        const float4 L2z1 = __ldg(pr + rowZ + 2 * rowY);

        const float ty0 = (float)(63 - 2 * p) * (1.0f / 63.0f);  // h0=2p
        const float ty1 = (float)(62 - 2 * p) * (1.0f / 63.0f);  // h1=2p+1
        const float sy0 = 1.0f - ty0;
        const float sy1 = 1.0f - ty1;

        const float a0 = sy0 * sz, b0w = ty0 * sz, c0 = sy0 * tz, e0 = ty0 * tz;
        g0.x = fmaf(e0, L1z1.x, fmaf(c0, L0z1.x, fmaf(b0w, L1z0.x, a0 * L0z0.x)));
        g0.y = fmaf(e0, L1z1.y, fmaf(c0, L0z1.y, fmaf(b0w, L1z0.y, a0 * L0z0.y)));
        g0.z = fmaf(e0, L1z1.z, fmaf(c0, L0z1.z, fmaf(b0w, L1z0.z, a0 * L0z0.z)));
        g0.w = fmaf(e0, L1z1.w, fmaf(c0, L0z1.w, fmaf(b0w, L1z0.w, a0 * L0z0.w)));

        const float a1 = sy1 * sz, b1w = ty1 * sz, c1 = sy1 * tz, e1 = ty1 * tz;
        g1.x = fmaf(e1, L2z1.x, fmaf(c1, L1z1.x, fmaf(b1w, L2z0.x, a1 * L1z0.x)));
        g1.y = fmaf(e1, L2z1.y, fmaf(c1, L1z1.y, fmaf(b1w, L2z0.y, a1 * L1z0.y)));
        g1.z = fmaf(e1, L2z1.z, fmaf(c1, L1z1.z, fmaf(b1w, L2z0.z, a1 * L1z0.z)));
        g1.w = fmaf(e1, L2z1.w, fmaf(c1, L1z1.w, fmaf(b1w, L2z0.w, a1 * L1z0.w)));
    }

    // g(x-1) from lane-8 (previous column, same c4)
    float4 gp0, gp1;
    gp0.x = __shfl_up_sync(0xFFFFFFFFu, g0.x, 8);
    gp0.y = __shfl_up_sync(0xFFFFFFFFu, g0.y, 8);
    gp0.z = __shfl_up_sync(0xFFFFFFFFu, g0.z, 8);
    gp0.w = __shfl_up_sync(0xFFFFFFFFu, g0.w, 8);
    gp1.x = __shfl_up_sync(0xFFFFFFFFu, g1.x, 8);
    gp1.y = __shfl_up_sync(0xFFFFFFFFu, g1.y, 8);
    gp1.z = __shfl_up_sync(0xFFFFFFFFu, g1.z, 8);
    gp1.w = __shfl_up_sync(0xFFFFFFFFu, g1.w, 8);

    const long voxRow0 = (((long)b * D_ + d) * H_ + h0) * W_;   // row h0
    const long voxRow1 = voxRow0 + W_;                           // row h1

    if (j > 0) {
        const float t = 1.0f - (float)x * (1.0f / 63.0f);  // x >= 1 here
        const float s = 1.0f - t;
        float4 r0, r1;
        r0.x = fmaf(t, g0.x, s * gp0.x);
        r0.y = fmaf(t, g0.y, s * gp0.y);
        r0.z = fmaf(t, g0.z, s * gp0.z);
        r0.w = fmaf(t, g0.w, s * gp0.w);
        r1.x = fmaf(t, g1.x, s * gp1.x);
        r1.y = fmaf(t, g1.y, s * gp1.y);
        r1.z = fmaf(t, g1.z, s * gp1.z);
        r1.w = fmaf(t, g1.w, s * gp1.w);
        out[(voxRow0 + x) * C4_ + c4] = r0;
        out[(voxRow1 + x) * C4_ + c4] = r1;
    } else if (seg == 0) {
        // x = 0: t = 0 -> out = g(0)
        out[voxRow0 * C4_ + c4] = g0;
        out[voxRow1 * C4_ + c4] = g1;
    }
}

extern "C" void kernel_launch(void* const* d_in, const int* in_sizes, int n_in,
                              void* d_out, int out_size)
{
    const float4* in = (const float4*)d_in[0];
    float4* out = (float4*)d_out;
    dim3 grid(SEGS_, (B_ * D_ * (H_ / 2)) / 8, 1);   // (21, 1024)
    trilerp_hp_kernel<<<grid, 256>>>(in, out);
}

// round 6
// speedup vs baseline: 1.1544x; 1.0126x over previous
#include <cuda_runtime.h>

// Trilinear resample (B=4, D=64, H=64, W=64, C=32) fp32, identity theta.
// f = 62*i/63 => i0 = max(i-1,0), t(i) = 1 - i/63 (t=0 at i=0).
//
// R5 warp-shuffle h-pair scheme + R6 change: STREAMING stores (__stcs) so the
// 134MB/replay output write stream is marked evict-first in L2, keeping the
// (almost L2-resident) 134MB input cached across graph replays.
//
// Warp layout: lane = c4(0..7) + 8*j (j=0..3); column x = 3*seg + j.
// Each lane serves rows h0=2p, h1=2p+1 (share middle y-row): 6 float4 loads,
// two (y,z)-bilinears, g(x-1) via shfl_up(8), lanes j>=1 emit 2 outputs.

#define B_ 4
#define D_ 64
#define H_ 64
#define W_ 64
#define C4_ 8
#define SEGS_ 21

__global__ __launch_bounds__(256) void trilerp_hp_cs_kernel(
    const float4* __restrict__ in, float4* __restrict__ out)
{
    const int lane = threadIdx.x & 31;
    const int wid  = threadIdx.x >> 5;       // 0..7
    const int c4 = lane & (C4_ - 1);
    const int j  = lane >> 3;                // 0..3

    const int seg = blockIdx.x;              // 0..20
    const int by  = blockIdx.y;              // 0..1023
    const int pg  = by & 3;
    const int d   = (by >> 2) & (D_ - 1);
    const int b   = by >> 8;
    const int p   = pg * 8 + wid;            // 0..31  (h-pair), warp-uniform
    const int h0  = 2 * p;
    const int x   = 3 * seg + j;             // 0..63

    // z weights
    const float fz = (float)d * (62.0f / 63.0f);
    const int z0 = max(d - 1, 0);
    const float tz = fz - (float)z0;
    const float sz = 1.0f - tz;

    const long rowY = (long)W_ * C4_;
    const long rowZ = (long)H_ * W_ * C4_;
    const float4* pb = in + (((long)b * D_ + z0) * (long)H_ * W_ + x) * C4_ + c4;

    float4 g0, g1;   // (y,z)-bilinear blends for rows h0, h1 at column x

    if (p == 0) {
        // h0=0 (ty0=0), h1=1 (ty1=62/63); both use y-rows {0,1}: 4 loads
        const float4 r0z0 = __ldg(pb);
        const float4 r1z0 = __ldg(pb + rowY);
        const float4 r0z1 = __ldg(pb + rowZ);
        const float4 r1z1 = __ldg(pb + rowZ + rowY);
        g0.x = fmaf(tz, r0z1.x, sz * r0z0.x);
        g0.y = fmaf(tz, r0z1.y, sz * r0z0.y);
        g0.z = fmaf(tz, r0z1.z, sz * r0z0.z);
        g0.w = fmaf(tz, r0z1.w, sz * r0z0.w);
        const float ty1 = 62.0f / 63.0f;
        const float sy1 = 1.0f - ty1;
        const float a = sy1 * sz, bw = ty1 * sz, c = sy1 * tz, e = ty1 * tz;
        g1.x = fmaf(e, r1z1.x, fmaf(c, r0z1.x, fmaf(bw, r1z0.x, a * r0z0.x)));
        g1.y = fmaf(e, r1z1.y, fmaf(c, r0z1.y, fmaf(bw, r1z0.y, a * r0z0.y)));
        g1.z = fmaf(e, r1z1.z, fmaf(c, r0z1.z, fmaf(bw, r1z0.z, a * r0z0.z)));
        g1.w = fmaf(e, r1z1.w, fmaf(c, r0z1.w, fmaf(bw, r1z0.w, a * r0z0.w)));
    } else {
        // rows 2p-1, 2p, 2p+1; g0 uses (2p-1,2p), g1 uses (2p,2p+1): 6 loads
        const float4* pr = pb + (long)(h0 - 1) * rowY;
        const float4 L0z0 = __ldg(pr);
        const float4 L1z0 = __ldg(pr + rowY);
        const float4 L2z0 = __ldg(pr + 2 * rowY);
        const float4 L0z1 = __ldg(pr + rowZ);
        const float4 L1z1 = __ldg(pr + rowZ + rowY);
        const float4 L2z1 = __ldg(pr + rowZ + 2 * rowY);

        const float ty0 = (float)(63 - 2 * p) * (1.0f / 63.0f);
        const float ty1 = (float)(62 - 2 * p) * (1.0f / 63.0f);
        const float sy0 = 1.0f - ty0;
        const float sy1 = 1.0f - ty1;

        const float a0 = sy0 * sz, b0w = ty0 * sz, c0 = sy0 * tz, e0 = ty0 * tz;
        g0.x = fmaf(e0, L1z1.x, fmaf(c0, L0z1.x, fmaf(b0w, L1z0.x, a0 * L0z0.x)));
        g0.y = fmaf(e0, L1z1.y, fmaf(c0, L0z1.y, fmaf(b0w, L1z0.y, a0 * L0z0.y)));
        g0.z = fmaf(e0, L1z1.z, fmaf(c0, L0z1.z, fmaf(b0w, L1z0.z, a0 * L0z0.z)));
        g0.w = fmaf(e0, L1z1.w, fmaf(c0, L0z1.w, fmaf(b0w, L1z0.w, a0 * L0z0.w)));

        const float a1 = sy1 * sz, b1w = ty1 * sz, c1 = sy1 * tz, e1 = ty1 * tz;
        g1.x = fmaf(e1, L2z1.x, fmaf(c1, L1z1.x, fmaf(b1w, L2z0.x, a1 * L1z0.x)));
        g1.y = fmaf(e1, L2z1.y, fmaf(c1, L1z1.y, fmaf(b1w, L2z0.y, a1 * L1z0.y)));
        g1.z = fmaf(e1, L2z1.z, fmaf(c1, L1z1.z, fmaf(b1w, L2z0.z, a1 * L1z0.z)));
        g1.w = fmaf(e1, L2z1.w, fmaf(c1, L1z1.w, fmaf(b1w, L2z0.w, a1 * L1z0.w)));
    }

    // g(x-1) from lane-8 (previous column, same c4)
    float4 gp0, gp1;
    gp0.x = __shfl_up_sync(0xFFFFFFFFu, g0.x, 8);
    gp0.y = __shfl_up_sync(0xFFFFFFFFu, g0.y, 8);
    gp0.z = __shfl_up_sync(0xFFFFFFFFu, g0.z, 8);
    gp0.w = __shfl_up_sync(0xFFFFFFFFu, g0.w, 8);
    gp1.x = __shfl_up_sync(0xFFFFFFFFu, g1.x, 8);
    gp1.y = __shfl_up_sync(0xFFFFFFFFu, g1.y, 8);
    gp1.z = __shfl_up_sync(0xFFFFFFFFu, g1.z, 8);
    gp1.w = __shfl_up_sync(0xFFFFFFFFu, g1.w, 8);

    const long voxRow0 = (((long)b * D_ + d) * H_ + h0) * W_;
    const long voxRow1 = voxRow0 + W_;

    if (j > 0) {
        const float t = 1.0f - (float)x * (1.0f / 63.0f);  // x >= 1 here
        const float s = 1.0f - t;
        float4 r0, r1;
        r0.x = fmaf(t, g0.x, s * gp0.x);
        r0.y = fmaf(t, g0.y, s * gp0.y);
        r0.z = fmaf(t, g0.z, s * gp0.z);
        r0.w = fmaf(t, g0.w, s * gp0.w);
        r1.x = fmaf(t, g1.x, s * gp1.x);
        r1.y = fmaf(t, g1.y, s * gp1.y);
        r1.z = fmaf(t, g1.z, s * gp1.z);
        r1.w = fmaf(t, g1.w, s * gp1.w);
        __stcs(out + (voxRow0 + x) * C4_ + c4, r0);   // streaming: evict-first in L2
        __stcs(out + (voxRow1 + x) * C4_ + c4, r1);
    } else if (seg == 0) {
        __stcs(out + voxRow0 * C4_ + c4, g0);
        __stcs(out + voxRow1 * C4_ + c4, g1);
    }
}

extern "C" void kernel_launch(void* const* d_in, const int* in_sizes, int n_in,
                              void* d_out, int out_size)
{
    const float4* in = (const float4*)d_in[0];
    float4* out = (float4*)d_out;
    dim3 grid(SEGS_, (B_ * D_ * (H_ / 2)) / 8, 1);   // (21, 1024)
    trilerp_hp_cs_kernel<<<grid, 256>>>(in, out);
}

// round 7
// speedup vs baseline: 1.1755x; 1.0183x over previous
#include <cuda_runtime.h>

// Trilinear resample (B=4, D=64, H=64, W=64, C=32) fp32, identity theta.
// f = 62*i/63 => i0 = max(i-1,0), t(i) = 1 - i/63 (t=0 at i=0).
//
// R5 warp-shuffle h-pair scheme + R7 change: WRITE-THROUGH stores (__stwt)
// so the 134MB output stream does not allocate L2 lines, leaving L2 to hold
// the 134MB input across graph replays (L2 = 126MB; reads become mostly hits).
//
// Warp layout: lane = c4(0..7) + 8*j (j=0..3); column x = 3*seg + j.
// Each lane serves rows h0=2p, h1=2p+1 (share middle y-row): 6 float4 loads,
// two (y,z)-bilinears, g(x-1) via shfl_up(8), lanes j>=1 emit 2 outputs.

#define B_ 4
#define D_ 64
#define H_ 64
#define W_ 64
#define C4_ 8
#define SEGS_ 21

__global__ __launch_bounds__(256) void trilerp_hp_wt_kernel(
    const float4* __restrict__ in, float4* __restrict__ out)
{
    const int lane = threadIdx.x & 31;
    const int wid  = threadIdx.x >> 5;       // 0..7
    const int c4 = lane & (C4_ - 1);
    const int j  = lane >> 3;                // 0..3

    const int seg = blockIdx.x;              // 0..20
    const int by  = blockIdx.y;              // 0..1023
    const int pg  = by & 3;
    const int d   = (by >> 2) & (D_ - 1);
    const int b   = by >> 8;
    const int p   = pg * 8 + wid;            // 0..31  (h-pair), warp-uniform
    const int h0  = 2 * p;
    const int x   = 3 * seg + j;             // 0..63

    // z weights
    const float fz = (float)d * (62.0f / 63.0f);
    const int z0 = max(d - 1, 0);
    const float tz = fz - (float)z0;
    const float sz = 1.0f - tz;

    const long rowY = (long)W_ * C4_;
    const long rowZ = (long)H_ * W_ * C4_;
    const float4* pb = in + (((long)b * D_ + z0) * (long)H_ * W_ + x) * C4_ + c4;

    float4 g0, g1;   // (y,z)-bilinear blends for rows h0, h1 at column x

    if (p == 0) {
        // h0=0 (ty0=0), h1=1 (ty1=62/63); both use y-rows {0,1}: 4 loads
        const float4 r0z0 = __ldg(pb);
        const float4 r1z0 = __ldg(pb + rowY);
        const float4 r0z1 = __ldg(pb + rowZ);
        const float4 r1z1 = __ldg(pb + rowZ + rowY);
        g0.x = fmaf(tz, r0z1.x, sz * r0z0.x);
        g0.y = fmaf(tz, r0z1.y, sz * r0z0.y);
        g0.z = fmaf(tz, r0z1.z, sz * r0z0.z);
        g0.w = fmaf(tz, r0z1.w, sz * r0z0.w);
        const float ty1 = 62.0f / 63.0f;
        const float sy1 = 1.0f - ty1;
        const float a = sy1 * sz, bw = ty1 * sz, c = sy1 * tz, e = ty1 * tz;
        g1.x = fmaf(e, r1z1.x, fmaf(c, r0z1.x, fmaf(bw, r1z0.x, a * r0z0.x)));
        g1.y = fmaf(e, r1z1.y, fmaf(c, r0z1.y, fmaf(bw, r1z0.y, a * r0z0.y)));
        g1.z = fmaf(e, r1z1.z, fmaf(c, r0z1.z, fmaf(bw, r1z0.z, a * r0z0.z)));
        g1.w = fmaf(e, r1z1.w, fmaf(c, r0z1.w, fmaf(bw, r1z0.w, a * r0z0.w)));
    } else {
        // rows 2p-1, 2p, 2p+1; g0 uses (2p-1,2p), g1 uses (2p,2p+1): 6 loads
        const float4* pr = pb + (long)(h0 - 1) * rowY;
        const float4 L0z0 = __ldg(pr);
        const float4 L1z0 = __ldg(pr + rowY);
        const float4 L2z0 = __ldg(pr + 2 * rowY);
        const float4 L0z1 = __ldg(pr + rowZ);
        const float4 L1z1 = __ldg(pr + rowZ + rowY);
        const float4 L2z1 = __ldg(pr + rowZ + 2 * rowY);

        const float ty0 = (float)(63 - 2 * p) * (1.0f / 63.0f);
        const float ty1 = (float)(62 - 2 * p) * (1.0f / 63.0f);
        const float sy0 = 1.0f - ty0;
        const float sy1 = 1.0f - ty1;

        const float a0 = sy0 * sz, b0w = ty0 * sz, c0 = sy0 * tz, e0 = ty0 * tz;
        g0.x = fmaf(e0, L1z1.x, fmaf(c0, L0z1.x, fmaf(b0w, L1z0.x, a0 * L0z0.x)));
        g0.y = fmaf(e0, L1z1.y, fmaf(c0, L0z1.y, fmaf(b0w, L1z0.y, a0 * L0z0.y)));
        g0.z = fmaf(e0, L1z1.z, fmaf(c0, L0z1.z, fmaf(b0w, L1z0.z, a0 * L0z0.z)));
        g0.w = fmaf(e0, L1z1.w, fmaf(c0, L0z1.w, fmaf(b0w, L1z0.w, a0 * L0z0.w)));

        const float a1 = sy1 * sz, b1w = ty1 * sz, c1 = sy1 * tz, e1 = ty1 * tz;
        g1.x = fmaf(e1, L2z1.x, fmaf(c1, L1z1.x, fmaf(b1w, L2z0.x, a1 * L1z0.x)));
        g1.y = fmaf(e1, L2z1.y, fmaf(c1, L1z1.y, fmaf(b1w, L2z0.y, a1 * L1z0.y)));
        g1.z = fmaf(e1, L2z1.z, fmaf(c1, L1z1.z, fmaf(b1w, L2z0.z, a1 * L1z0.z)));
        g1.w = fmaf(e1, L2z1.w, fmaf(c1, L1z1.w, fmaf(b1w, L2z0.w, a1 * L1z0.w)));
    }

    // g(x-1) from lane-8 (previous column, same c4)
    float4 gp0, gp1;
    gp0.x = __shfl_up_sync(0xFFFFFFFFu, g0.x, 8);
    gp0.y = __shfl_up_sync(0xFFFFFFFFu, g0.y, 8);
    gp0.z = __shfl_up_sync(0xFFFFFFFFu, g0.z, 8);
    gp0.w = __shfl_up_sync(0xFFFFFFFFu, g0.w, 8);
    gp1.x = __shfl_up_sync(0xFFFFFFFFu, g1.x, 8);
    gp1.y = __shfl_up_sync(0xFFFFFFFFu, g1.y, 8);
    gp1.z = __shfl_up_sync(0xFFFFFFFFu, g1.z, 8);
    gp1.w = __shfl_up_sync(0xFFFFFFFFu, g1.w, 8);

    const long voxRow0 = (((long)b * D_ + d) * H_ + h0) * W_;
    const long voxRow1 = voxRow0 + W_;

    if (j > 0) {
        const float t = 1.0f - (float)x * (1.0f / 63.0f);  // x >= 1 here
        const float s = 1.0f - t;
        float4 r0, r1;
        r0.x = fmaf(t, g0.x, s * gp0.x);
        r0.y = fmaf(t, g0.y, s * gp0.y);
        r0.z = fmaf(t, g0.z, s * gp0.z);
        r0.w = fmaf(t, g0.w, s * gp0.w);
        r1.x = fmaf(t, g1.x, s * gp1.x);
        r1.y = fmaf(t, g1.y, s * gp1.y);
        r1.z = fmaf(t, g1.z, s * gp1.z);
        r1.w = fmaf(t, g1.w, s * gp1.w);
        __stwt(out + (voxRow0 + x) * C4_ + c4, r0);   // write-through: no L2 alloc
        __stwt(out + (voxRow1 + x) * C4_ + c4, r1);
    } else if (seg == 0) {
        __stwt(out + voxRow0 * C4_ + c4, g0);
        __stwt(out + voxRow1 * C4_ + c4, g1);
    }
}

extern "C" void kernel_launch(void* const* d_in, const int* in_sizes, int n_in,
                              void* d_out, int out_size)
{
    const float4* in = (const float4*)d_in[0];
    float4* out = (float4*)d_out;
    dim3 grid(SEGS_, (B_ * D_ * (H_ / 2)) / 8, 1);   // (21, 1024)
    trilerp_hp_wt_kernel<<<grid, 256>>>(in, out);
}

// round 8
// speedup vs baseline: 1.1894x; 1.0118x over previous
#include <cuda_runtime.h>

// Trilinear resample (B=4, D=64, H=64, W=64, C=32) fp32, identity theta.
// f = 62*i/63 => i0 = max(i-1,0), t(i) = 1 - i/63 (t=0 at i=0).
//
// R5 warp-shuffle h-pair scheme, work-looped: each block handles all 4 pg
// groups for one (b,d) (unroll 2 => two independent 6-load chains in flight
// per warp), z-weights hoisted. Plain stores (cache hints proved inert).
//
// Warp layout: lane = c4(0..7) + 8*j (j=0..3); column x = 3*seg + j.
// Per iter: lane serves rows h0=2p, h1=2p+1 (share middle y-row): 6 loads,
// two (y,z)-bilinears, g(x-1) via shfl_up(8), lanes j>=1 emit 2 outputs.

#define B_ 4
#define D_ 64
#define H_ 64
#define W_ 64
#define C4_ 8
#define SEGS_ 21

__global__ __launch_bounds__(256) void trilerp_hp_loop_kernel(
    const float4* __restrict__ in, float4* __restrict__ out)
{
    const int lane = threadIdx.x & 31;
    const int wid  = threadIdx.x >> 5;       // 0..7
    const int c4 = lane & (C4_ - 1);
    const int j  = lane >> 3;                // 0..3

    const int seg = blockIdx.x;              // 0..20
    const int bd  = blockIdx.y;              // 0..255
    const int d   = bd & (D_ - 1);
    const int b   = bd >> 6;
    const int x   = 3 * seg + j;             // 0..63

    // z weights (hoisted: fixed per block)
    const float fz = (float)d * (62.0f / 63.0f);
    const int z0 = max(d - 1, 0);
    const float tz = fz - (float)z0;
    const float sz = 1.0f - tz;

    const long rowY = (long)W_ * C4_;
    const long rowZ = (long)H_ * W_ * C4_;
    const float4* pb = in + (((long)b * D_ + z0) * (long)H_ * W_ + x) * C4_ + c4;

    const long voxBase = (((long)b * D_ + d) * H_) * W_;  // row h -> voxBase + h*W_

    #pragma unroll 2
    for (int pg = 0; pg < 4; ++pg) {
        const int p  = pg * 8 + wid;          // 0..31, warp-uniform
        const int h0 = 2 * p;

        float4 g0, g1;   // (y,z)-bilinear blends for rows h0, h1 at column x

        if (p == 0) {
            // h0=0 (ty0=0), h1=1 (ty1=62/63); both use y-rows {0,1}: 4 loads
            const float4 r0z0 = __ldg(pb);
            const float4 r1z0 = __ldg(pb + rowY);
            const float4 r0z1 = __ldg(pb + rowZ);
            const float4 r1z1 = __ldg(pb + rowZ + rowY);
            g0.x = fmaf(tz, r0z1.x, sz * r0z0.x);
            g0.y = fmaf(tz, r0z1.y, sz * r0z0.y);
            g0.z = fmaf(tz, r0z1.z, sz * r0z0.z);
            g0.w = fmaf(tz, r0z1.w, sz * r0z0.w);
            const float ty1 = 62.0f / 63.0f;
            const float sy1 = 1.0f - ty1;
            const float a = sy1 * sz, bw = ty1 * sz, c = sy1 * tz, e = ty1 * tz;
            g1.x = fmaf(e, r1z1.x, fmaf(c, r0z1.x, fmaf(bw, r1z0.x, a * r0z0.x)));
            g1.y = fmaf(e, r1z1.y, fmaf(c, r0z1.y, fmaf(bw, r1z0.y, a * r0z0.y)));
            g1.z = fmaf(e, r1z1.z, fmaf(c, r0z1.z, fmaf(bw, r1z0.z, a * r0z0.z)));
            g1.w = fmaf(e, r1z1.w, fmaf(c, r0z1.w, fmaf(bw, r1z0.w, a * r0z0.w)));
        } else {
            // rows 2p-1, 2p, 2p+1; g0 uses (2p-1,2p), g1 uses (2p,2p+1): 6 loads
            const float4* pr = pb + (long)(h0 - 1) * rowY;
            const float4 L0z0 = __ldg(pr);
            const float4 L1z0 = __ldg(pr + rowY);
            const float4 L2z0 = __ldg(pr + 2 * rowY);
            const float4 L0z1 = __ldg(pr + rowZ);
            const float4 L1z1 = __ldg(pr + rowZ + rowY);
            const float4 L2z1 = __ldg(pr + rowZ + 2 * rowY);

            const float ty0 = (float)(63 - 2 * p) * (1.0f / 63.0f);
            const float ty1 = (float)(62 - 2 * p) * (1.0f / 63.0f);
            const float sy0 = 1.0f - ty0;
            const float sy1 = 1.0f - ty1;

            const float a0 = sy0 * sz, b0w = ty0 * sz, c0 = sy0 * tz, e0 = ty0 * tz;
            g0.x = fmaf(e0, L1z1.x, fmaf(c0, L0z1.x, fmaf(b0w, L1z0.x, a0 * L0z0.x)));
            g0.y = fmaf(e0, L1z1.y, fmaf(c0, L0z1.y, fmaf(b0w, L1z0.y, a0 * L0z0.y)));
            g0.z = fmaf(e0, L1z1.z, fmaf(c0, L0z1.z, fmaf(b0w, L1z0.z, a0 * L0z0.z)));
            g0.w = fmaf(e0, L1z1.w, fmaf(c0, L0z1.w, fmaf(b0w, L1z0.w, a0 * L0z0.w)));

            const float a1 = sy1 * sz, b1w = ty1 * sz, c1 = sy1 * tz, e1 = ty1 * tz;
            g1.x = fmaf(e1, L2z1.x, fmaf(c1, L1z1.x, fmaf(b1w, L2z0.x, a1 * L1z0.x)));
            g1.y = fmaf(e1, L2z1.y, fmaf(c1, L1z1.y, fmaf(b1w, L2z0.y, a1 * L1z0.y)));
            g1.z = fmaf(e1, L2z1.z, fmaf(c1, L1z1.z, fmaf(b1w, L2z0.z, a1 * L1z0.z)));
            g1.w = fmaf(e1, L2z1.w, fmaf(c1, L1z1.w, fmaf(b1w, L2z0.w, a1 * L1z0.w)));
        }

        // g(x-1) from lane-8 (previous column, same c4)
        float4 gp0, gp1;
        gp0.x = __shfl_up_sync(0xFFFFFFFFu, g0.x, 8);
        gp0.y = __shfl_up_sync(0xFFFFFFFFu, g0.y, 8);
        gp0.z = __shfl_up_sync(0xFFFFFFFFu, g0.z, 8);
        gp0.w = __shfl_up_sync(0xFFFFFFFFu, g0.w, 8);
        gp1.x = __shfl_up_sync(0xFFFFFFFFu, g1.x, 8);
        gp1.y = __shfl_up_sync(0xFFFFFFFFu, g1.y, 8);
        gp1.z = __shfl_up_sync(0xFFFFFFFFu, g1.z, 8);
        gp1.w = __shfl_up_sync(0xFFFFFFFFu, g1.w, 8);

        const long voxRow0 = voxBase + (long)h0 * W_;
        const long voxRow1 = voxRow0 + W_;

        if (j > 0) {
            const float t = 1.0f - (float)x * (1.0f / 63.0f);  // x >= 1 here
            const float s = 1.0f - t;
            float4 r0, r1;
            r0.x = fmaf(t, g0.x, s * gp0.x);
            r0.y = fmaf(t, g0.y, s * gp0.y);
            r0.z = fmaf(t, g0.z, s * gp0.z);
            r0.w = fmaf(t, g0.w, s * gp0.w);
            r1.x = fmaf(t, g1.x, s * gp1.x);
            r1.y = fmaf(t, g1.y, s * gp1.y);
            r1.z = fmaf(t, g1.z, s * gp1.z);
            r1.w = fmaf(t, g1.w, s * gp1.w);
            out[(voxRow0 + x) * C4_ + c4] = r0;
            out[(voxRow1 + x) * C4_ + c4] = r1;
        } else if (seg == 0) {
            // x = 0: t = 0 -> out = g(0)
            out[voxRow0 * C4_ + c4] = g0;
            out[voxRow1 * C4_ + c4] = g1;
        }
    }
}

extern "C" void kernel_launch(void* const* d_in, const int* in_sizes, int n_in,
                              void* d_out, int out_size)
{
    const float4* in = (const float4*)d_in[0];
    float4* out = (float4*)d_out;
    dim3 grid(SEGS_, B_ * D_, 1);   // (21, 256) -> 5376 blocks
    trilerp_hp_loop_kernel<<<grid, 256>>>(in, out);
}